// round 4
// baseline (speedup 1.0000x reference)
#include <cuda_runtime.h>
#include <math.h>

#define NN 4
#define MM 1128
#define LL 512
#define NF 13
#define NEG_BIG 100000.0f

// scratch for d = ||H1-H2||^2, shape [N, M]
__device__ float g_d[NN * MM];

// ---------------------------------------------------------------------------
// Kernel 1: per (b,m) pair -> self-attention pooling for both X1 and X2,
// then squared distance of pooled vectors.
// grid = N*M blocks, 256 threads each.
// ---------------------------------------------------------------------------
__global__ __launch_bounds__(256) void pool_kernel(
    const float* __restrict__ X1, const float* __restrict__ X2,
    const float* __restrict__ M1, const float* __restrict__ M2,
    const float* __restrict__ attn_w)
{
    __shared__ __align__(16) float Xs[LL * NF];  // 6656 floats = 26624 B, float4-accessed
    __shared__ float As[NF * NF];      // A = attn_w^T
    __shared__ float red[8 * NF];      // per-warp partials of H
    __shared__ float sred[16];         // [0..7]=max partials, [8..15]=sum partials
    __shared__ float Hout[2][NF];

    const int bm   = blockIdx.x;
    const int tid  = threadIdx.x;
    const int warp = tid >> 5;
    const int lane = tid & 31;

    if (tid < NF * NF) {
        int i = tid / NF, j = tid % NF;
        As[i * NF + j] = attn_w[j * NF + i];   // A[i][j] = attn_w[j][i]
    }

    const float* Xp[2] = {X1, X2};
    const float* Mp[2] = {M1, M2};
    const size_t base = (size_t)bm * (LL * NF);

    for (int side = 0; side < 2; ++side) {
        // issue the two strided mask loads early so their DRAM latency
        // overlaps the cooperative tile load below
        const float m0a = Mp[side][base + (size_t)(tid)       * NF];
        const float m0b = Mp[side][base + (size_t)(tid + 256) * NF];

        __syncthreads();  // (a) As ready / previous iteration's smem use done

        // cooperative coalesced load of the X tile (26624 B, 16B aligned)
        {
            const float4* src = (const float4*)(Xp[side] + base);
            float4* dst = (float4*)Xs;
            #pragma unroll
            for (int k = tid; k < (LL * NF) / 4; k += 256) dst[k] = src[k];
        }
        __syncthreads();  // (b)

        // --- scores + mask for 2 positions per thread ---
        float logit[2];
        #pragma unroll
        for (int p = 0; p < 2; ++p) {
            const int l = tid + p * 256;
            const float* xr = &Xs[l * NF];
            float s = 0.0f;
            #pragma unroll
            for (int i = 0; i < NF; ++i) {
                float y = 0.0f;
                #pragma unroll
                for (int j = 0; j < NF; ++j) y += As[i * NF + j] * xr[j];
                s += xr[i] * y;
            }
            const float m0 = (p == 0) ? m0a : m0b;
            logit[p] = tanhf(s) + (m0 - 1.0f) * NEG_BIG;
        }

        // --- block max over 512 logits ---
        float mx = fmaxf(logit[0], logit[1]);
        #pragma unroll
        for (int o = 16; o; o >>= 1) mx = fmaxf(mx, __shfl_xor_sync(0xffffffffu, mx, o));
        if (lane == 0) sred[warp] = mx;
        __syncthreads();  // (c)
        float bmax = sred[0];
        #pragma unroll
        for (int w = 1; w < 8; ++w) bmax = fmaxf(bmax, sred[w]);

        // --- exp + block sum ---
        const float e0 = expf(logit[0] - bmax);
        const float e1 = expf(logit[1] - bmax);
        float sum = e0 + e1;
        #pragma unroll
        for (int o = 16; o; o >>= 1) sum += __shfl_xor_sync(0xffffffffu, sum, o);
        if (lane == 0) sred[8 + warp] = sum;
        __syncthreads();  // (d)
        float bsum = 0.0f;
        #pragma unroll
        for (int w = 0; w < 8; ++w) bsum += sred[8 + w];
        const float inv = 1.0f / bsum;
        const float w0 = e0 * inv, w1 = e1 * inv;

        // --- weighted sum H = sum_l W_l x_l ---
        float hpart[NF];
        {
            const float* x0 = &Xs[(tid)       * NF];
            const float* x1 = &Xs[(tid + 256) * NF];
            #pragma unroll
            for (int i = 0; i < NF; ++i) hpart[i] = w0 * x0[i] + w1 * x1[i];
        }
        #pragma unroll
        for (int i = 0; i < NF; ++i) {
            float v = hpart[i];
            #pragma unroll
            for (int o = 16; o; o >>= 1) v += __shfl_xor_sync(0xffffffffu, v, o);
            if (lane == 0) red[warp * NF + i] = v;
        }
        __syncthreads();  // (e)
        if (tid < NF) {
            float h = 0.0f;
            #pragma unroll
            for (int w = 0; w < 8; ++w) h += red[w * NF + tid];
            Hout[side][tid] = h;
        }
    }

    __syncthreads();
    if (tid == 0) {
        float d = 0.0f;
        #pragma unroll
        for (int i = 0; i < NF; ++i) {
            float t = Hout[0][i] - Hout[1][i];
            d += t * t;
        }
        g_d[bm] = d;
    }
}

// ---------------------------------------------------------------------------
// Kernel 2: out[n,i] = sum_j d[n,j] * layer_w[i,j] + layer_b[i]
// grid = 282 blocks, each handles 4 output columns; 128 threads.
// ---------------------------------------------------------------------------
__global__ __launch_bounds__(128) void fc_kernel(
    const float* __restrict__ layer_w,
    const float* __restrict__ layer_b,
    float* __restrict__ out)
{
    const int tid  = threadIdx.x;
    const int warp = tid >> 5;
    const int lane = tid & 31;
    __shared__ float r[4][NN];

    for (int c = 0; c < 4; ++c) {
        const int i = blockIdx.x * 4 + c;

        float acc[NN] = {0.f, 0.f, 0.f, 0.f};
        const float* wr = layer_w + (size_t)i * MM;
        for (int j = tid; j < MM; j += 128) {
            const float w = wr[j];
            #pragma unroll
            for (int n = 0; n < NN; ++n) acc[n] += g_d[n * MM + j] * w;
        }
        #pragma unroll
        for (int n = 0; n < NN; ++n) {
            #pragma unroll
            for (int o = 16; o; o >>= 1)
                acc[n] += __shfl_xor_sync(0xffffffffu, acc[n], o);
        }
        if (lane == 0) {
            #pragma unroll
            for (int n = 0; n < NN; ++n) r[warp][n] = acc[n];
        }
        __syncthreads();
        if (tid == 0) {
            const float b = layer_b[i];
            #pragma unroll
            for (int n = 0; n < NN; ++n)
                out[n * MM + i] = r[0][n] + r[1][n] + r[2][n] + r[3][n] + b;
        }
        __syncthreads();
    }
}

extern "C" void kernel_launch(void* const* d_in, const int* in_sizes, int n_in,
                              void* d_out, int out_size)
{
    const float* X1      = (const float*)d_in[0];
    const float* X2      = (const float*)d_in[1];
    const float* M1      = (const float*)d_in[2];
    const float* M2      = (const float*)d_in[3];
    const float* attn_w  = (const float*)d_in[4];
    const float* layer_w = (const float*)d_in[5];
    const float* layer_b = (const float*)d_in[6];
    float* out = (float*)d_out;

    pool_kernel<<<NN * MM, 256>>>(X1, X2, M1, M2, attn_w);
    fc_kernel<<<MM / 4, 128>>>(layer_w, layer_b, out);
}